// round 8
// baseline (speedup 1.0000x reference)
#include <cuda_runtime.h>
#include <cstdint>
#include <cstddef>

#define N_CAM 6
#define C_CH  128
#define H_IMG 64
#define W_IMG 176
#define HW    (H_IMG * W_IMG)     // 11264
#define NQ    640000              // 200*200*16

#define T_BLOCKS ((HW / 32) * (C_CH / 32) * N_CAM)   // 8448 transpose blocks
#define I_BLOCKS (NQ / 256)                          // 2500 index blocks
#define P_BLOCKS (T_BLOCKS + I_BLOCKS)               // 10948
// Interleave: for bid < 4*I_BLOCKS, every 4th block (bid%4==3) is an index
// block; the rest (and everything above) are transpose blocks -> both roles
// co-resident from wave 0.
#define I_SPAN (4 * I_BLOCKS)                        // 10000

// Scratch: img_feats transposed to (cam, h, w, c): query's 128 channels are
// 512 contiguous bytes. 34.6 MB static __device__ (alloc-free).
__device__ float g_scratch[(size_t)N_CAM * HW * C_CH];
// Per-query packed spatial index into scratch (element-row index), -1 invalid.
__device__ int g_idx[NQ];

// ---- cache-hinted accessors (createpolicy + L2::cache_hint) ----------------
__device__ __forceinline__ unsigned long long policy_evict_last() {
    unsigned long long p;
    asm("createpolicy.fractional.L2::evict_last.b64 %0, 1.0;" : "=l"(p));
    return p;
}
__device__ __forceinline__ void stg_el(float* ptr, float v, unsigned long long pol) {
    asm volatile("st.global.L2::cache_hint.f32 [%0], %1, %2;"
                 :: "l"(ptr), "f"(v), "l"(pol));
}

// ---------------------------------------------------------------------------
// Fused prologue, role-interleaved. Prologue is bandwidth-bound (~90MB), so
// the index role loads points ONLY for the selected cam (dependent load; its
// latency hides behind the co-resident transpose blocks).
// ---------------------------------------------------------------------------
__global__ __launch_bounds__(256) void prologue_kernel(
    const float* __restrict__ img,
    const float* __restrict__ pts,
    const void*  __restrict__ valid)
{
    const int tid = threadIdx.x;
    const int bid = blockIdx.x;
    const bool is_index = (bid < I_SPAN) && ((bid & 3) == 3);

    if (!is_index) {
        // ---- transpose role: (C,HW) -> (HW,C) per cam, 32x32 tiles --------
        const int t_id = (bid < I_SPAN) ? (bid - ((bid + 1) >> 2))
                                        : (bid - I_BLOCKS);
        __shared__ float tile[32][33];
        int b = t_id;
        const int cam = b / ((HW / 32) * (C_CH / 32));
        b -= cam * ((HW / 32) * (C_CH / 32));
        const int cb  = b / (HW / 32);
        const int hwb = b - cb * (HW / 32);
        const int hw0 = hwb * 32;
        const int c0  = cb * 32;
        const int tx = tid & 31, ty = tid >> 5;     // 32 x 8

        const unsigned long long pol = policy_evict_last();
        const float* src = img + (size_t)cam * C_CH * HW;
        float*       dst = g_scratch + (size_t)cam * HW * C_CH;

#pragma unroll
        for (int k = 0; k < 4; k++) {
            int c = c0 + ty + k * 8;
            tile[ty + k * 8][tx] = __ldcs(&src[(size_t)c * HW + hw0 + tx]);
        }
        __syncthreads();
#pragma unroll
        for (int k = 0; k < 4; k++) {
            int hw = hw0 + ty + k * 8;
            stg_el(&dst[(size_t)hw * C_CH + c0 + tx], tile[tx][ty + k * 8], pol);
        }
    } else {
        // ---- index role: cam-select + round-to-nearest-even (jnp.round) ---
        // Valid dtype detected per block: a 1-byte bool array has ~30%
        // nonzero bytes at offsets ≡ 1 (mod 4); int32/f32 encodings of 0/1
        // have 0x00 there. 1024 samples -> P(false negative) ~ 0.7^1024.
        const int q = (bid >> 2) * 256 + tid;
        const unsigned char* vb = (const unsigned char*)valid;
        const unsigned int*  vw = (const unsigned int*)valid;

        int found = 0;
#pragma unroll
        for (int j = 0; j < 4; j++)
            if (vb[1 + 4 * (tid * 4 + j)] != 0) found = 1;
        const int isByte = __syncthreads_or(found);

        int cam = -1;
        if (isByte) {
#pragma unroll
            for (int cc = 0; cc < N_CAM; cc++)
                if (vb[(size_t)cc * NQ + q] != 0) cam = cc;
        } else {
#pragma unroll
            for (int cc = 0; cc < N_CAM; cc++)
                if (vw[(size_t)cc * NQ + q] != 0u) cam = cc;
        }

        int p = -1;
        if (cam >= 0) {
            float2 sp = __ldg(&((const float2*)pts)[(size_t)cam * NQ + q]);
            int x = min(max(__float2int_rn(sp.x), 0), W_IMG - 1);
            int y = min(max(__float2int_rn(sp.y), 0), H_IMG - 1);
            p = cam * HW + y * W_IMG + x;
        }
        g_idx[q] = p;
    }
}

// ---------------------------------------------------------------------------
// Gather: tile = 32 queries x 128 channels, 16KB smem -> 8 resident blocks/SM
// (64 warps, 100% occupancy) to cover the exposed L2/DRAM latency.
// XOR-swizzled float4 layout: slot(q, f4) = q*32 + (f4 ^ q), q < 32.
// Phase A: cp.async.cg (L2->smem direct); invalid queries zero-fill via the
//   src-size=0 operand; idx preloaded by 4 lanes (16B coalesced) + shuffle.
// Phase B: conflict-free LDS.128 (lane l reads q=l, banks c4^l) + 4 coalesced
//   128B STG.32 streams (__stcs evict-first: the 328MB output stream must not
//   evict the L2-resident scratch).
// ---------------------------------------------------------------------------
__global__ __launch_bounds__(256) void gather_kernel(float* __restrict__ out)
{
    __shared__ float4 sm4[32 * 32];     // 16 KB
    const int tid = threadIdx.x;
    const int w = tid >> 5, l = tid & 31;
    const int q0 = blockIdx.x * 32;

    const unsigned long long pol = policy_evict_last();
    const float4* scr4 = (const float4*)g_scratch;

    int pv = 0;
    if (l < 4) pv = g_idx[q0 + w * 4 + l];

    const unsigned int smem_base =
        (unsigned int)__cvta_generic_to_shared(sm4);

#pragma unroll
    for (int i = 0; i < 4; i++) {
        const int p = __shfl_sync(0xffffffffu, pv, i);
        const int q = w * 4 + i;                 // local query 0..31
        const unsigned int dst =
            smem_base + (unsigned int)((q * 32 + (l ^ q)) * 16);
        const float4* src = scr4 + (size_t)max(p, 0) * 32 + l;
        const int sz = (p >= 0) ? 16 : 0;        // 0 -> 16B zero-fill
        asm volatile(
            "cp.async.cg.shared.global.L2::cache_hint [%0], [%1], 16, %2, %3;"
            :: "r"(dst), "l"(src), "r"(sz), "l"(pol) : "memory");
    }
    asm volatile("cp.async.commit_group;" ::: "memory");
    asm volatile("cp.async.wait_group 0;" ::: "memory");
    __syncthreads();

#pragma unroll
    for (int j = 0; j < 4; j++) {
        const int c4 = w * 4 + j;                // float4 channel group 0..31
        const int q = l;
        float4 v = sm4[q * 32 + (c4 ^ q)];
        const size_t gq = (size_t)q0 + q;
        __stcs(&out[(size_t)(4 * c4 + 0) * NQ + gq], v.x);
        __stcs(&out[(size_t)(4 * c4 + 1) * NQ + gq], v.y);
        __stcs(&out[(size_t)(4 * c4 + 2) * NQ + gq], v.z);
        __stcs(&out[(size_t)(4 * c4 + 3) * NQ + gq], v.w);
    }
}

// ---------------------------------------------------------------------------
extern "C" void kernel_launch(void* const* d_in, const int* in_sizes, int n_in,
                              void* d_out, int out_size) {
    const float* img   = (const float*)d_in[0];   // (6,128,64,176) f32
    const float* pts   = (const float*)d_in[1];   // (6,640000,2)  f32
    const void*  valid = d_in[2];                 // (6,640000) bool-ish
    float*       out   = (float*)d_out;           // (128,200,200,16) f32

    prologue_kernel<<<P_BLOCKS, 256>>>(img, pts, valid);
    gather_kernel<<<NQ / 32, 256>>>(out);
}